// round 6
// baseline (speedup 1.0000x reference)
#include <cuda_runtime.h>
#include <cstdint>

// ---------------------------------------------------------------------------
// Neck: 3 x (modulated deformable 3x3 conv -> ConvTranspose2d(k3,s2,p1,op1))
//  - off/mod convs: fused-im2col GEMM (M=27 pad 32), split-K when N small
//  - deform conv:   FUSED deformable-im2col GEMM (smem bilinear tables),
//                   split-K when N small. No col buffer.
//  - tconv:         parity-decomposed, all 4 parities batched in one launch
//  All GEMMs: pre-transposed A + double-buffered smem pipeline.
// ---------------------------------------------------------------------------

#define BATCH 8

__device__ float g_bufA[8388608];    // deform outputs Y
__device__ float g_bufB[16777216];   // tconv outputs
__device__ float g_offmod[3538944];  // [B,27,HW] off+mod conv out
__device__ float g_part[8388608];    // split-K partials (max 4*256*8192)
__device__ float g_womT[147456];     // [K,32] transposed padded off/mod weights
__device__ float g_bom[32];
__device__ float g_wT[1179648];      // [K9,O] transposed deform weights
__device__ float g_wtpT[589824];     // transposed parity tconv weights

// ---------------------------------------------------------------------------
// Weight prep
// ---------------------------------------------------------------------------
__global__ void transpose_w(const float* __restrict__ src, float* __restrict__ dst,
                            int M, int K) {
    int idx = blockIdx.x * blockDim.x + threadIdx.x;
    if (idx >= M * K) return;
    int m = idx / K;
    int k = idx - m * K;
    dst[(size_t)k * M + m] = src[idx];
}

__global__ void build_womT(const float* __restrict__ w_off, const float* __restrict__ b_off,
                           const float* __restrict__ w_mod, const float* __restrict__ b_mod,
                           float* __restrict__ womT, float* __restrict__ bom, int K) {
    int idx = blockIdx.x * blockDim.x + threadIdx.x;
    if (idx < 32) bom[idx] = (idx < 18) ? b_off[idx] : (idx < 27 ? b_mod[idx - 18] : 0.f);
    if (idx >= 32 * K) return;
    int k = idx >> 5;
    int m = idx & 31;
    float v = 0.f;
    if (m < 18)      v = w_off[(size_t)m * K + k];
    else if (m < 27) v = w_mod[(size_t)(m - 18) * K + k];
    womT[idx] = v;
}

// parity regions at float offsets {0,1,3,5}*O*O, layout [Kp][O], k=c*nt+t
__global__ void build_wtpT(const float* __restrict__ wt, float* __restrict__ out, int O) {
    int idx = blockIdx.x * blockDim.x + threadIdx.x;
    int OO = O * O;
    if (idx >= 9 * OO) return;
    int p, base, nt;
    if (idx < OO)          { p = 0; base = 0;      nt = 1; }
    else if (idx < 3 * OO) { p = 1; base = OO;     nt = 2; }
    else if (idx < 5 * OO) { p = 2; base = 3 * OO; nt = 2; }
    else                   { p = 3; base = 5 * OO; nt = 4; }
    int r = idx - base;
    int o = r % O;
    int k = r / O;
    int c = k / nt;
    int t = k - c * nt;
    int ry = p >> 1, rx = p & 1;
    int ntx = rx + 1;
    int tyi = t / ntx;
    int txi = t - tyi * ntx;
    int ky = ry ? (tyi ? 2 : 0) : 1;
    int kx = rx ? (txi ? 2 : 0) : 1;
    out[idx] = wt[((size_t)(c * O + o)) * 9 + ky * 3 + kx];
}

// ---------------------------------------------------------------------------
// split-K reduce: out NCHW = sum_s part[s][m][n] + bias[m]
// ---------------------------------------------------------------------------
__global__ void reduce_part(const float* __restrict__ part, const float* __restrict__ bias,
                            float* __restrict__ out, int M, int Mpad, int N, int HW, int S) {
    int idx = blockIdx.x * blockDim.x + threadIdx.x;
    int nv = N >> 2;
    if (idx >= M * nv) return;
    int m = idx / nv;
    int n4 = (idx - m * nv) << 2;
    size_t off = (size_t)m * N + n4;
    float4 s = *reinterpret_cast<const float4*>(&part[off]);
    size_t sl = (size_t)Mpad * N;
    for (int si = 1; si < S; si++) {
        float4 p = *reinterpret_cast<const float4*>(&part[(size_t)si * sl + off]);
        s.x += p.x; s.y += p.y; s.z += p.z; s.w += p.w;
    }
    float bv = bias[m];
    s.x += bv; s.y += bv; s.z += bv; s.w += bv;
    int b = n4 / HW;
    int hw = n4 - b * HW;
    *reinterpret_cast<float4*>(&out[((size_t)(b * M + m)) * HW + hw]) = s;
}

// ---------------------------------------------------------------------------
// GEMM core. A pre-transposed At[K][lda]. Double buffered, BK=8, BN=128,
// 256 threads, TN=8.
// ---------------------------------------------------------------------------
#define GEMM_COMPUTE(BUF)                                                 \
    _Pragma("unroll")                                                     \
    for (int kk = 0; kk < 8; kk++) {                                      \
        float ar[TM], br[8];                                              \
        _Pragma("unroll")                                                 \
        for (int i = 0; i < TM; i++) ar[i] = As[BUF][kk][ty * TM + i];    \
        _Pragma("unroll")                                                 \
        for (int j = 0; j < 8; j++) br[j] = Bs[BUF][kk][tx * 8 + j];      \
        _Pragma("unroll")                                                 \
        for (int i = 0; i < TM; i++)                                      \
            _Pragma("unroll")                                             \
            for (int j = 0; j < 8; j++) acc[i][j] += ar[i] * br[j];       \
    }

// ---------------------------------------------------------------------------
// Fused deformable-conv SGEMM. B[k= c*9+t][n] generated on the fly from
// per-block smem tables of bilinear weights (mod folded in) and clamped
// indices, which depend only on (t, n) — amortized over all channels.
// ---------------------------------------------------------------------------
template<int BM, int TM>
__global__ __launch_bounds__(256) void sgemm_dcn(
        const float* __restrict__ At, const float* __restrict__ X,
        const float* __restrict__ om,
        const float* __restrict__ bias, float* __restrict__ Out,
        float* __restrict__ part,
        int M, int C, int N, int H, int W, int Kslice) {
    __shared__ float As[2][8][BM];
    __shared__ float Bs[2][8][128];
    __shared__ float4 Twgt[9][128];     // bilinear weights * sigmoid(mod)
    __shared__ ushort4 Tidx[9][128];    // clamped hw indices (HW <= 16384)
    __shared__ int TbOff[128];          // b * C * HW per column

    const int tid = threadIdx.x;
    const int mBase = blockIdx.y * BM;
    const int nBase = blockIdx.x * 128;
    const int kBegin = blockIdx.z * Kslice;
    const int kEnd = kBegin + Kslice;
    constexpr int TPR = BM / 4;
    const int aRow = tid / TPR;
    const int aCol = (tid % TPR) * 4;
    const bool aAct = (tid < 8 * TPR);
    const int bRow = tid >> 5, bCol = (tid & 31) << 2;
    const int ty = tid >> 4, tx = tid & 15;
    const int HW = H * W;

    // ---- build bilinear tables: 9 taps x 128 columns ----
    for (int e = tid; e < 9 * 128; e += 256) {
        int t = e >> 7;
        int j = e & 127;
        int n = nBase + j;
        int b = n / HW;
        int hw = n - b * HW;
        int h = hw / W, w = hw - (hw / W) * W;
        if (t == 0) TbOff[j] = b * C * HW;

        float dy = om[((size_t)(b * 27 + 2 * t)) * HW + hw];
        float dx = om[((size_t)(b * 27 + 2 * t + 1)) * HW + hw];
        float mr = om[((size_t)(b * 27 + 18 + t)) * HW + hw];
        float m  = 1.f / (1.f + expf(-mr));

        float py = dy + (float)(t / 3 - 1) + (float)h;
        float px = dx + (float)(t % 3 - 1) + (float)w;

        float y0f = floorf(py), x0f = floorf(px);
        float wy = py - y0f, wx = px - x0f;
        int y0 = (int)y0f, x0 = (int)x0f;
        int y1 = y0 + 1,   x1 = x0 + 1;

        bool vy0 = (y0 >= 0) && (y0 <= H - 1);
        bool vy1 = (y1 >= 0) && (y1 <= H - 1);
        bool vx0 = (x0 >= 0) && (x0 <= W - 1);
        bool vx1 = (x1 >= 0) && (x1 <= W - 1);

        int y0c = min(max(y0, 0), H - 1);
        int y1c = min(max(y1, 0), H - 1);
        int x0c = min(max(x0, 0), W - 1);
        int x1c = min(max(x1, 0), W - 1);

        float4 wv;
        wv.x = (1.f - wy) * (1.f - wx) * ((vy0 && vx0) ? m : 0.f);
        wv.y = (1.f - wy) * wx         * ((vy0 && vx1) ? m : 0.f);
        wv.z = wy * (1.f - wx)         * ((vy1 && vx0) ? m : 0.f);
        wv.w = wy * wx                 * ((vy1 && vx1) ? m : 0.f);
        Twgt[t][j] = wv;
        Tidx[t][j] = make_ushort4((unsigned short)(y0c * W + x0c),
                                  (unsigned short)(y0c * W + x1c),
                                  (unsigned short)(y1c * W + x0c),
                                  (unsigned short)(y1c * W + x1c));
    }
    __syncthreads();

    float acc[TM][8] = {};
    float4 aReg;
    float bv[4];

#define DCN_GATHER(K0)                                                    \
    {                                                                     \
        int kr = (K0) + bRow;                                             \
        int c = kr / 9;                                                   \
        int t = kr - c * 9;                                               \
        int cOff = c * HW;                                                \
        _Pragma("unroll")                                                 \
        for (int j = 0; j < 4; j++) {                                     \
            int jj = bCol + j;                                            \
            float4 wv = Twgt[t][jj];                                      \
            ushort4 ii = Tidx[t][jj];                                     \
            const float* xb = X + TbOff[jj] + cOff;                       \
            bv[j] = wv.x * xb[ii.x] + wv.y * xb[ii.y]                     \
                  + wv.z * xb[ii.z] + wv.w * xb[ii.w];                    \
        }                                                                 \
    }

    aReg = aAct ? *reinterpret_cast<const float4*>(&At[(size_t)(kBegin + aRow) * M + mBase + aCol])
                : make_float4(0.f, 0.f, 0.f, 0.f);
    DCN_GATHER(kBegin);
    if (aAct) *reinterpret_cast<float4*>(&As[0][aRow][aCol]) = aReg;
#pragma unroll
    for (int j = 0; j < 4; j++) Bs[0][bRow][bCol + j] = bv[j];
    __syncthreads();

    int buf = 0;
    for (int k0 = kBegin + 8; k0 < kEnd; k0 += 8) {
        aReg = aAct ? *reinterpret_cast<const float4*>(&At[(size_t)(k0 + aRow) * M + mBase + aCol])
                    : make_float4(0.f, 0.f, 0.f, 0.f);
        DCN_GATHER(k0);
        GEMM_COMPUTE(buf);
        if (aAct) *reinterpret_cast<float4*>(&As[buf ^ 1][aRow][aCol]) = aReg;
#pragma unroll
        for (int j = 0; j < 4; j++) Bs[buf ^ 1][bRow][bCol + j] = bv[j];
        buf ^= 1;
        __syncthreads();
    }
    GEMM_COMPUTE(buf);
#undef DCN_GATHER

    if (part) {
        float* p = part + (size_t)blockIdx.z * M * N;
#pragma unroll
        for (int i = 0; i < TM; i++) {
            int m = mBase + ty * TM + i;
#pragma unroll
            for (int j = 0; j < 8; j += 4) {
                int n = nBase + tx * 8 + j;
                *reinterpret_cast<float4*>(&p[(size_t)m * N + n]) =
                    make_float4(acc[i][j], acc[i][j + 1], acc[i][j + 2], acc[i][j + 3]);
            }
        }
    } else {
        int bI[8], hwI[8];
#pragma unroll
        for (int j = 0; j < 8; j++) {
            int n = nBase + tx * 8 + j;
            bI[j] = n / HW; hwI[j] = n - bI[j] * HW;
        }
#pragma unroll
        for (int i = 0; i < TM; i++) {
            int m = mBase + ty * TM + i;
            float bvl = bias[m];
#pragma unroll
            for (int j = 0; j < 8; j++)
                Out[((size_t)(bI[j] * M + m)) * HW + hwI[j]] = acc[i][j] + bvl;
        }
    }
}

// ---- fused 3x3-conv SGEMM (off/mod, M=27 pad 32), optional split-K ----
template<int BM, int TM>
__global__ __launch_bounds__(256) void sgemm_c3x3(
        const float* __restrict__ At, const float* __restrict__ X,
        const float* __restrict__ bias, float* __restrict__ Out,
        float* __restrict__ part,
        int M, int C, int N, int H, int W, int Kslice) {
    __shared__ float As[2][8][BM];
    __shared__ float Bs[2][8][128];
    const int tid = threadIdx.x;
    const int nBase = blockIdx.x * 128;
    const int kBegin = blockIdx.z * Kslice;
    const int kEnd = kBegin + Kslice;
    constexpr int TPR = BM / 4;
    const int aRow = tid / TPR;
    const int aCol = (tid % TPR) * 4;
    const bool aAct = (tid < 8 * TPR);
    const int bRow = tid >> 5, bCol = (tid & 31) << 2;
    const int ty = tid >> 4, tx = tid & 15;
    const int HW = H * W;

    int ny[4], nx[4];
    size_t nbOff[4];
#pragma unroll
    for (int j = 0; j < 4; j++) {
        int n = nBase + bCol + j;
        int b = n / HW;
        int hw = n - b * HW;
        ny[j] = hw / W; nx[j] = hw - ny[j] * W;
        nbOff[j] = (size_t)b * C * HW;
    }

    float acc[TM][8] = {};
    float4 aReg;
    float bv[4];

#define C3X3_GATHER(K0)                                                       \
    {                                                                         \
        int kr = (K0) + bRow;                                                 \
        int c = kr / 9;                                                       \
        int t = kr - c * 9;                                                   \
        int q = t / 3;                                                        \
        int dy = q - 1, dx = t - q * 3 - 1;                                   \
        size_t cOff = (size_t)c * HW;                                         \
        _Pragma("unroll")                                                     \
        for (int j = 0; j < 4; j++) {                                         \
            int iy = ny[j] + dy, ix = nx[j] + dx;                             \
            bv[j] = ((unsigned)iy < (unsigned)H && (unsigned)ix < (unsigned)W) \
                        ? X[nbOff[j] + cOff + iy * W + ix] : 0.f;             \
        }                                                                     \
    }

    aReg = aAct ? *reinterpret_cast<const float4*>(&At[(size_t)(kBegin + aRow) * BM + aCol])
                : make_float4(0.f, 0.f, 0.f, 0.f);
    C3X3_GATHER(kBegin);
    if (aAct) *reinterpret_cast<float4*>(&As[0][aRow][aCol]) = aReg;
#pragma unroll
    for (int j = 0; j < 4; j++) Bs[0][bRow][bCol + j] = bv[j];
    __syncthreads();

    int buf = 0;
    for (int k0 = kBegin + 8; k0 < kEnd; k0 += 8) {
        aReg = aAct ? *reinterpret_cast<const float4*>(&At[(size_t)(k0 + aRow) * BM + aCol])
                    : make_float4(0.f, 0.f, 0.f, 0.f);
        C3X3_GATHER(k0);
        GEMM_COMPUTE(buf);
        if (aAct) *reinterpret_cast<float4*>(&As[buf ^ 1][aRow][aCol]) = aReg;
#pragma unroll
        for (int j = 0; j < 4; j++) Bs[buf ^ 1][bRow][bCol + j] = bv[j];
        buf ^= 1;
        __syncthreads();
    }
    GEMM_COMPUTE(buf);
#undef C3X3_GATHER

    if (part) {
        float* p = part + (size_t)blockIdx.z * BM * N;
#pragma unroll
        for (int i = 0; i < TM; i++) {
            int m = ty * TM + i;
#pragma unroll
            for (int j = 0; j < 8; j += 4) {
                int n = nBase + tx * 8 + j;
                *reinterpret_cast<float4*>(&p[(size_t)m * N + n]) =
                    make_float4(acc[i][j], acc[i][j + 1], acc[i][j + 2], acc[i][j + 3]);
            }
        }
    } else {
        int bI[8], hwI[8];
#pragma unroll
        for (int j = 0; j < 8; j++) {
            int n = nBase + tx * 8 + j;
            bI[j] = n / HW; hwI[j] = n - bI[j] * HW;
        }
#pragma unroll
        for (int i = 0; i < TM; i++) {
            int m = ty * TM + i;
            if (m >= M) continue;
            float bvl = bias[m];
#pragma unroll
            for (int j = 0; j < 8; j++)
                Out[((size_t)(bI[j] * M + m)) * HW + hwI[j]] = acc[i][j] + bvl;
        }
    }
}

// ---- batched parity transposed-conv SGEMM: blockIdx.z = parity 0..3 ----
template<int BM, int TM>
__global__ __launch_bounds__(256) void sgemm_tconv(
        const float* __restrict__ AtAll, const float* __restrict__ X,
        const float* __restrict__ bias, float* __restrict__ Out,
        int O, int N, int H, int W) {
    __shared__ float As[2][8][BM];
    __shared__ float Bs[2][8][128];
    const int tid = threadIdx.x;
    const int p = blockIdx.z;
    const int ry = p >> 1, rx = p & 1;
    const int lnt = (p == 0) ? 0 : (p == 3) ? 2 : 1;
    const int ntm1 = (1 << lnt) - 1;
    const int K = O << lnt;
    const int OO = O * O;
    const float* At = AtAll + (size_t)OO * ((p == 0) ? 0 : (p == 1) ? 1 : (p == 2) ? 3 : 5);

    const int mBase = blockIdx.y * BM;
    const int nBase = blockIdx.x * 128;
    constexpr int TPR = BM / 4;
    const int aRow = tid / TPR;
    const int aCol = (tid % TPR) * 4;
    const bool aAct = (tid < 8 * TPR);
    const int bRow = tid >> 5, bCol = (tid & 31) << 2;
    const int ty = tid >> 4, tx = tid & 15;
    const int HW = H * W;

    int ny[4], nx[4];
    size_t nbOff[4];
#pragma unroll
    for (int j = 0; j < 4; j++) {
        int n = nBase + bCol + j;
        int b = n / HW;
        int hw = n - b * HW;
        ny[j] = hw / W; nx[j] = hw - ny[j] * W;
        nbOff[j] = (size_t)b * O * HW;
    }

    float acc[TM][8] = {};
    float4 aReg;
    float bv[4];

#define TC_GATHER(K0)                                                 \
    {                                                                 \
        int kr = (K0) + bRow;                                         \
        int c = kr >> lnt;                                            \
        int t = kr & ntm1;                                            \
        int tyi = t >> rx;                                            \
        int txi = t & rx;                                             \
        int dy = ry * (1 - tyi);                                      \
        int dx = rx * (1 - txi);                                      \
        size_t cOff = (size_t)c * HW;                                 \
        _Pragma("unroll")                                             \
        for (int j = 0; j < 4; j++) {                                 \
            int iy = ny[j] + dy, ix = nx[j] + dx;                     \
            bv[j] = (iy < H && ix < W)                                \
                        ? X[nbOff[j] + cOff + iy * W + ix] : 0.f;     \
        }                                                             \
    }

    aReg = aAct ? *reinterpret_cast<const float4*>(&At[(size_t)aRow * O + mBase + aCol])
                : make_float4(0.f, 0.f, 0.f, 0.f);
    TC_GATHER(0);
    if (aAct) *reinterpret_cast<float4*>(&As[0][aRow][aCol]) = aReg;
#pragma unroll
    for (int j = 0; j < 4; j++) Bs[0][bRow][bCol + j] = bv[j];
    __syncthreads();

    int buf = 0;
    for (int k0 = 8; k0 < K; k0 += 8) {
        aReg = aAct ? *reinterpret_cast<const float4*>(&At[(size_t)(k0 + aRow) * O + mBase + aCol])
                    : make_float4(0.f, 0.f, 0.f, 0.f);
        TC_GATHER(k0);
        GEMM_COMPUTE(buf);
        if (aAct) *reinterpret_cast<float4*>(&As[buf ^ 1][aRow][aCol]) = aReg;
#pragma unroll
        for (int j = 0; j < 4; j++) Bs[buf ^ 1][bRow][bCol + j] = bv[j];
        buf ^= 1;
        __syncthreads();
    }
    GEMM_COMPUTE(buf);
#undef TC_GATHER

    int bI[8], yI[8], xI[8];
#pragma unroll
    for (int j = 0; j < 8; j++) {
        int n = nBase + tx * 8 + j;
        int b = n / HW;
        int hw = n - b * HW;
        bI[j] = b; yI[j] = hw / W; xI[j] = hw - yI[j] * W;
    }
    int OH = 2 * H, OW = 2 * W;
#pragma unroll
    for (int i = 0; i < TM; i++) {
        int m = mBase + ty * TM + i;
        float bvl = bias[m];
#pragma unroll
        for (int j = 0; j < 8; j++) {
            int oy = 2 * yI[j] + ry;
            int ox = 2 * xI[j] + rx;
            Out[((size_t)(bI[j] * O + m) * OH + oy) * OW + ox] = acc[i][j] + bvl;
        }
    }
}

// ---------------------------------------------------------------------------
static inline float* symaddr(const void* sym) {
    void* p = nullptr;
    cudaGetSymbolAddress(&p, sym);
    return (float*)p;
}

extern "C" void kernel_launch(void* const* d_in, const int* in_sizes, int n_in,
                              void* d_out, int out_size) {
    float* bufA  = symaddr(g_bufA);
    float* bufB  = symaddr(g_bufB);
    float* omb   = symaddr(g_offmod);
    float* partb = symaddr(g_part);
    float* womT  = symaddr(g_womT);
    float* bom   = symaddr(g_bom);
    float* wT    = symaddr(g_wT);
    float* wtpT  = symaddr(g_wtpT);

    struct Stage {
        const float *w_off, *b_off, *w_mod, *b_mod, *w, *b, *wt, *bt;
        int C, H, W, O;
    };
    Stage st[3];
    for (int i = 0; i < 3; i++) {
        int base = 1 + i * 8;
        st[i].w_off = (const float*)d_in[base + 0];
        st[i].b_off = (const float*)d_in[base + 1];
        st[i].w_mod = (const float*)d_in[base + 2];
        st[i].b_mod = (const float*)d_in[base + 3];
        st[i].w     = (const float*)d_in[base + 4];
        st[i].b     = (const float*)d_in[base + 5];
        st[i].wt    = (const float*)d_in[base + 6];
        st[i].bt    = (const float*)d_in[base + 7];
    }
    st[0].C = 512; st[0].H = 32;  st[0].W = 32;  st[0].O = 256;
    st[1].C = 256; st[1].H = 64;  st[1].W = 64;  st[1].O = 128;
    st[2].C = 128; st[2].H = 128; st[2].W = 128; st[2].O = 64;

    // split-K configs per stage
    const int S_c3[3]  = {8, 2, 1};
    const int S_dcn[3] = {4, 2, 1};

    const float* X = (const float*)d_in[0];

    for (int i = 0; i < 3; i++) {
        int C = st[i].C, H = st[i].H, W = st[i].W, O = st[i].O;
        int HW = H * W;
        int N = BATCH * HW;
        int K9 = C * 9;

        // weight prep
        build_womT<<<(32 * K9 + 255) / 256, 256>>>(st[i].w_off, st[i].b_off,
                                                   st[i].w_mod, st[i].b_mod,
                                                   womT, bom, K9);
        transpose_w<<<(O * K9 + 255) / 256, 256>>>(st[i].w, wT, O, K9);
        build_wtpT<<<(9 * O * O + 255) / 256, 256>>>(st[i].wt, wtpT, O);

        // off/mod conv (fused im2col GEMM, M=27 pad 32)
        {
            int S = S_c3[i];
            if (S > 1) {
                sgemm_c3x3<32, 2><<<dim3(N / 128, 1, S), 256>>>(
                    womT, X, nullptr, nullptr, partb, 27, C, N, H, W, K9 / S);
                reduce_part<<<(27 * (N / 4) + 255) / 256, 256>>>(
                    partb, bom, omb, 27, 32, N, HW, S);
            } else {
                sgemm_c3x3<32, 2><<<dim3(N / 128, 1, 1), 256>>>(
                    womT, X, bom, omb, nullptr, 27, C, N, H, W, K9);
            }
        }

        // fused deformable-conv GEMM (no col buffer)
        float* Y = bufA;
        {
            int S = S_dcn[i];
            if (O >= 128) {
                if (S > 1) {
                    sgemm_dcn<128, 8><<<dim3(N / 128, O / 128, S), 256>>>(
                        wT, X, omb, nullptr, nullptr, partb, O, C, N, H, W, K9 / S);
                    reduce_part<<<(O * (N / 4) + 255) / 256, 256>>>(
                        partb, st[i].b, Y, O, O, N, HW, S);
                } else {
                    sgemm_dcn<128, 8><<<dim3(N / 128, O / 128, 1), 256>>>(
                        wT, X, omb, st[i].b, Y, nullptr, O, C, N, H, W, K9);
                }
            } else {
                sgemm_dcn<64, 4><<<dim3(N / 128, 1, 1), 256>>>(
                    wT, X, omb, st[i].b, Y, nullptr, O, C, N, H, W, K9);
            }
        }

        // parity-decomposed transposed conv: all 4 parities in one launch
        float* Xn = (i == 2) ? (float*)d_out : bufB;
        if (O >= 128)
            sgemm_tconv<128, 8><<<dim3(N / 128, O / 128, 4), 256>>>(
                wtpT, Y, st[i].bt, Xn, O, N, H, W);
        else
            sgemm_tconv<64, 4><<<dim3(N / 128, 1, 4), 256>>>(
                wtpT, Y, st[i].bt, Xn, O, N, H, W);

        X = Xn;
    }
}